// round 6
// baseline (speedup 1.0000x reference)
#include <cuda_runtime.h>
#include <cuda_fp16.h>

#define NUM_USERS 30000
#define NN 60000            // total nodes
#define EE 800000           // edges
#define KK 64               // embed dim (4 intents x 16)
#define NB 235              // ceil(NN/256) scan blocks

// -------- device scratch --------
__device__ __half d_TT16[(size_t)NN * KK];   // fp16 tanh(per-intent l2norm(ego))
__device__ __half d_EGO16[(size_t)NN * KK];  // fp16 rs1[n]*ego[n]  (attention path)
__device__ float  d_SC[(size_t)EE * 4];      // softmax scores at SORTED edge pos
__device__ int    d_deg[NN];
__device__ float  d_deg2[NN * 4];            // node-major [n][intent]
__device__ int    d_rowptr[NN + 1];
__device__ int    d_cursor[NN];
__device__ int    d_sorted_t[EE];            // tails grouped by head
__device__ int    d_partial[256];            // scan block sums

__device__ __forceinline__ const float4* ego_row(const float* Gu, const float* Gi, int t) {
    const float* p = (t < NUM_USERS) ? (Gu + (size_t)t * KK)
                                     : (Gi + (size_t)(t - NUM_USERS) * KK);
    return reinterpret_cast<const float4*>(p);
}

__device__ __forceinline__ float4 h4_to_f4(uint2 p) {
    float2 a = __half22float2(*reinterpret_cast<const __half2*>(&p.x));
    float2 b = __half22float2(*reinterpret_cast<const __half2*>(&p.y));
    return make_float4(a.x, a.y, b.x, b.y);
}

// softmax over intents; "1+" and max-shift cancel algebraically.
// returns score on all lanes; hm = half-warp mask.
__device__ __forceinline__ float edge_attn(float4 hv, float4 b, unsigned hm) {
    float p = hv.x * b.x + hv.y * b.y + hv.z * b.z + hv.w * b.w;
    p += __shfl_xor_sync(hm, p, 1);
    p += __shfl_xor_sync(hm, p, 2);
    float ex = __expf(p);
    float sum = ex + __shfl_xor_sync(hm, ex, 4);
    sum += __shfl_xor_sync(hm, sum, 8);
    return __fdividef(ex, sum);
}

// block-wide exclusive scan of one int per thread (blockDim=256)
__device__ __forceinline__ int block_exscan(int v, int* sm) {
    int lane = threadIdx.x & 31, w = threadIdx.x >> 5;
    int x = v;
#pragma unroll
    for (int d = 1; d < 32; d <<= 1) {
        int y = __shfl_up_sync(0xffffffffu, x, d);
        if (lane >= d) x += y;
    }
    if (lane == 31) sm[w] = x;
    __syncthreads();
    if (w == 0) {
        int s = (lane < 8) ? sm[lane] : 0;
#pragma unroll
        for (int d = 1; d < 8; d <<= 1) {
            int y = __shfl_up_sync(0xffffffffu, s, d);
            if (lane >= d) s += y;
        }
        if (lane < 8) sm[lane] = s;
    }
    __syncthreads();
    int off = (w > 0) ? sm[w - 1] : 0;
    return off + x - v;
}

// -------- kernels --------

__global__ void k_deg(const int* __restrict__ eh) {
    int g = blockIdx.x * blockDim.x + threadIdx.x;
    if (g >= EE / 4) return;
    int4 h4 = reinterpret_cast<const int4*>(eh)[g];
    atomicAdd(&d_deg[h4.x], 1);
    atomicAdd(&d_deg[h4.y], 1);
    atomicAdd(&d_deg[h4.z], 1);
    atomicAdd(&d_deg[h4.w], 1);
}

__global__ void k_s1() {
    __shared__ int sm[8];
    int i = blockIdx.x * 256 + threadIdx.x;
    int v = (i < NN) ? d_deg[i] : 0;
    int ex = block_exscan(v, sm);
    if (threadIdx.x == 255) d_partial[blockIdx.x] = ex + v;
}

__global__ void k_scan() {
    __shared__ int sm[8];
    __shared__ int base_sh;
    if (threadIdx.x < 32) {
        int s = 0;
        for (int t = threadIdx.x; t < blockIdx.x; t += 32) s += d_partial[t];
#pragma unroll
        for (int d = 16; d >= 1; d >>= 1) s += __shfl_xor_sync(0xffffffffu, s, d);
        if (threadIdx.x == 0) base_sh = s;
    }
    int i = blockIdx.x * 256 + threadIdx.x;
    int v = (i < NN) ? d_deg[i] : 0;
    int ex = block_exscan(v, sm);           // has __syncthreads (publishes base_sh)
    ex += base_sh;
    if (i < NN) { d_rowptr[i] = ex; d_cursor[i] = ex; }
    if (i == NN - 1) d_rowptr[NN] = EE;
}

#define SCAT_BLKS ((EE / 4 + 255) / 256)
#define NODE_BLKS ((NN * 16 + 255) / 256)

// fused: blocks [0, SCAT_BLKS) scatter tails; rest compute TT16 + EGO16
__global__ void k_scatter_node(const int* __restrict__ eh, const int* __restrict__ et,
                               const float* __restrict__ Gu, const float* __restrict__ Gi) {
    if (blockIdx.x < SCAT_BLKS) {
        int g = blockIdx.x * blockDim.x + threadIdx.x;
        if (g >= EE / 4) return;
        int4 h4 = __ldg(&reinterpret_cast<const int4*>(eh)[g]);
        int4 t4 = __ldg(&reinterpret_cast<const int4*>(et)[g]);
        d_sorted_t[atomicAdd(&d_cursor[h4.x], 1)] = t4.x;
        d_sorted_t[atomicAdd(&d_cursor[h4.y], 1)] = t4.y;
        d_sorted_t[atomicAdd(&d_cursor[h4.z], 1)] = t4.z;
        d_sorted_t[atomicAdd(&d_cursor[h4.w], 1)] = t4.w;
    } else {
        int tid = (blockIdx.x - SCAT_BLKS) * blockDim.x + threadIdx.x;
        if (tid >= NN * 16) return;
        int n = tid >> 4, c = tid & 15;
        float4 v = __ldg(&ego_row(Gu, Gi, n)[c]);
        float ss = v.x * v.x + v.y * v.y + v.z * v.z + v.w * v.w;
        ss += __shfl_xor_sync(0xffffffffu, ss, 1);
        ss += __shfl_xor_sync(0xffffffffu, ss, 2);
        float it = rsqrtf(fmaxf(ss, 1e-12f));
        __half2 t0 = __floats2half2_rn(tanhf(v.x * it), tanhf(v.y * it));
        __half2 t1 = __floats2half2_rn(tanhf(v.z * it), tanhf(v.w * it));
        uint2 tp; tp.x = *reinterpret_cast<unsigned*>(&t0);
                  tp.y = *reinterpret_cast<unsigned*>(&t1);
        reinterpret_cast<uint2*>(d_TT16)[tid] = tp;
        float w = rsqrtf((float)d_deg[n]);   // rs1 folded into EGO16
        __half2 e0 = __floats2half2_rn(w * v.x, w * v.y);
        __half2 e1 = __floats2half2_rn(w * v.z, w * v.w);
        uint2 ep; ep.x = *reinterpret_cast<unsigned*>(&e0);
                  ep.y = *reinterpret_cast<unsigned*>(&e1);
        reinterpret_cast<uint2*>(d_EGO16)[tid] = ep;
    }
}

// Fused warp-per-row: SpMM1 (fp16) -> in-register per-intent l2norm ->
// attention + softmax + SC + deg2. Row indices register-cached (tile of 32,
// per-half layout: lane hb+k holds index of edge j = start + 2k + half).
__global__ void k_row1attn() {
    int wid = (blockIdx.x * blockDim.x + threadIdx.x) >> 5;
    if (wid >= NN) return;
    int lane = threadIdx.x & 31, half = lane >> 4, c = lane & 15;
    unsigned hm = half ? 0xFFFF0000u : 0x0000FFFFu;
    int hb = half << 4;
    int start = d_rowptr[wid], end = d_rowptr[wid + 1];
    int deg = end - start;
    int cnt = (deg < 32) ? deg : 32;
    int pos = 2 * (lane & 15) + half;                 // edge slot this lane caches
    int idx0 = (pos < cnt) ? __ldg(&d_sorted_t[start + pos]) : 0;
    int mh = (cnt - half + 1) >> 1;                   // edges for this half in tile
    const uint2* EG = reinterpret_cast<const uint2*>(d_EGO16);
    const uint2* TT = reinterpret_cast<const uint2*>(d_TT16);

    // ---- pass 1: Z1 row accumulate (unroll-4, indices from registers) ----
    float4 acc = make_float4(0, 0, 0, 0);
    int m = 0;
    for (; m + 4 <= mh; m += 4) {
        int t0 = __shfl_sync(hm, idx0, hb + m);
        int t1 = __shfl_sync(hm, idx0, hb + m + 1);
        int t2 = __shfl_sync(hm, idx0, hb + m + 2);
        int t3 = __shfl_sync(hm, idx0, hb + m + 3);
        float4 s0 = h4_to_f4(__ldg(&EG[(size_t)t0 * 16 + c]));
        float4 s1 = h4_to_f4(__ldg(&EG[(size_t)t1 * 16 + c]));
        float4 s2 = h4_to_f4(__ldg(&EG[(size_t)t2 * 16 + c]));
        float4 s3 = h4_to_f4(__ldg(&EG[(size_t)t3 * 16 + c]));
        acc.x += (s0.x + s1.x) + (s2.x + s3.x);
        acc.y += (s0.y + s1.y) + (s2.y + s3.y);
        acc.z += (s0.z + s1.z) + (s2.z + s3.z);
        acc.w += (s0.w + s1.w) + (s2.w + s3.w);
    }
    for (; m < mh; m++) {
        int t = __shfl_sync(hm, idx0, hb + m);
        float4 s = h4_to_f4(__ldg(&EG[(size_t)t * 16 + c]));
        acc.x += s.x; acc.y += s.y; acc.z += s.z; acc.w += s.w;
    }
    for (int j = start + 32 + half; j < end; j += 2) {     // overflow (deg>32)
        int t = __ldg(&d_sorted_t[j]);
        float4 s = h4_to_f4(__ldg(&EG[(size_t)t * 16 + c]));
        acc.x += s.x; acc.y += s.y; acc.z += s.z; acc.w += s.w;
    }
    acc.x += __shfl_xor_sync(0xffffffffu, acc.x, 16);
    acc.y += __shfl_xor_sync(0xffffffffu, acc.y, 16);
    acc.z += __shfl_xor_sync(0xffffffffu, acc.z, 16);
    acc.w += __shfl_xor_sync(0xffffffffu, acc.w, 16);
    float ss = acc.x * acc.x + acc.y * acc.y + acc.z * acc.z + acc.w * acc.w;
    ss += __shfl_xor_sync(0xffffffffu, ss, 1);
    ss += __shfl_xor_sync(0xffffffffu, ss, 2);
    float ih = rsqrtf(fmaxf(ss, 1e-12f));
    float4 hv = make_float4(acc.x * ih, acc.y * ih, acc.z * ih, acc.w * ih);

    // ---- pass 2: attention + softmax + scores + deg2 (unroll-4 gathers) ----
    float dsum = 0.f;
    m = 0;
    for (; m + 4 <= mh; m += 4) {
        int t0 = __shfl_sync(hm, idx0, hb + m);
        int t1 = __shfl_sync(hm, idx0, hb + m + 1);
        int t2 = __shfl_sync(hm, idx0, hb + m + 2);
        int t3 = __shfl_sync(hm, idx0, hb + m + 3);
        float4 b0 = h4_to_f4(__ldg(&TT[(size_t)t0 * 16 + c]));
        float4 b1 = h4_to_f4(__ldg(&TT[(size_t)t1 * 16 + c]));
        float4 b2 = h4_to_f4(__ldg(&TT[(size_t)t2 * 16 + c]));
        float4 b3 = h4_to_f4(__ldg(&TT[(size_t)t3 * 16 + c]));
        float sc0 = edge_attn(hv, b0, hm);
        float sc1 = edge_attn(hv, b1, hm);
        float sc2 = edge_attn(hv, b2, hm);
        float sc3 = edge_attn(hv, b3, hm);
        if ((c & 3) == 0) {
            int i4 = c >> 2;
            d_SC[(size_t)(start + 2 * m + half) * 4 + i4] = sc0;
            d_SC[(size_t)(start + 2 * (m + 1) + half) * 4 + i4] = sc1;
            d_SC[(size_t)(start + 2 * (m + 2) + half) * 4 + i4] = sc2;
            d_SC[(size_t)(start + 2 * (m + 3) + half) * 4 + i4] = sc3;
            dsum += (sc0 + sc1) + (sc2 + sc3);
        }
    }
    for (; m < mh; m++) {
        int t = __shfl_sync(hm, idx0, hb + m);
        float4 b = h4_to_f4(__ldg(&TT[(size_t)t * 16 + c]));
        float sc = edge_attn(hv, b, hm);
        if ((c & 3) == 0) {
            d_SC[(size_t)(start + 2 * m + half) * 4 + (c >> 2)] = sc;
            dsum += sc;
        }
    }
    for (int j = start + 32 + half; j < end; j += 2) {     // overflow
        int t = __ldg(&d_sorted_t[j]);
        float4 b = h4_to_f4(__ldg(&TT[(size_t)t * 16 + c]));
        float sc = edge_attn(hv, b, hm);
        if ((c & 3) == 0) {
            d_SC[(size_t)j * 4 + (c >> 2)] = sc;
            dsum += sc;
        }
    }
    dsum += __shfl_xor_sync(0xffffffffu, dsum, 16);
    if (half == 0 && (c & 3) == 0)
        d_deg2[wid * 4 + (c >> 2)] = dsum;
}

// warp-per-row SpMM2 fused with rs2 (inline rsqrt) and final mean -> out.
// Same register index cache + unroll-4.
__global__ void k_row2(const float* __restrict__ Gu, const float* __restrict__ Gi,
                       float* __restrict__ out) {
    int wid = (blockIdx.x * blockDim.x + threadIdx.x) >> 5;
    if (wid >= NN) return;
    int lane = threadIdx.x & 31, half = lane >> 4, c = lane & 15;
    unsigned hm = half ? 0xFFFF0000u : 0x0000FFFFu;
    int hb = half << 4;
    int intent = c >> 2;
    int start = d_rowptr[wid], end = d_rowptr[wid + 1];
    int deg = end - start;
    int cnt = (deg < 32) ? deg : 32;
    int pos = 2 * (lane & 15) + half;
    int idx0 = (pos < cnt) ? __ldg(&d_sorted_t[start + pos]) : 0;
    int mh = (cnt - half + 1) >> 1;

    float4 acc = make_float4(0, 0, 0, 0);
    int m = 0;
    for (; m + 4 <= mh; m += 4) {
        int t0 = __shfl_sync(hm, idx0, hb + m);
        int t1 = __shfl_sync(hm, idx0, hb + m + 1);
        int t2 = __shfl_sync(hm, idx0, hb + m + 2);
        int t3 = __shfl_sync(hm, idx0, hb + m + 3);
        float w0 = __ldg(&d_SC[(size_t)(start + 2 * m + half) * 4 + intent]) *
                   rsqrtf(__ldg(&d_deg2[t0 * 4 + intent]));
        float w1 = __ldg(&d_SC[(size_t)(start + 2 * (m + 1) + half) * 4 + intent]) *
                   rsqrtf(__ldg(&d_deg2[t1 * 4 + intent]));
        float w2 = __ldg(&d_SC[(size_t)(start + 2 * (m + 2) + half) * 4 + intent]) *
                   rsqrtf(__ldg(&d_deg2[t2 * 4 + intent]));
        float w3 = __ldg(&d_SC[(size_t)(start + 2 * (m + 3) + half) * 4 + intent]) *
                   rsqrtf(__ldg(&d_deg2[t3 * 4 + intent]));
        float4 s0 = __ldg(&ego_row(Gu, Gi, t0)[c]);
        float4 s1 = __ldg(&ego_row(Gu, Gi, t1)[c]);
        float4 s2 = __ldg(&ego_row(Gu, Gi, t2)[c]);
        float4 s3 = __ldg(&ego_row(Gu, Gi, t3)[c]);
        acc.x += (w0 * s0.x + w1 * s1.x) + (w2 * s2.x + w3 * s3.x);
        acc.y += (w0 * s0.y + w1 * s1.y) + (w2 * s2.y + w3 * s3.y);
        acc.z += (w0 * s0.z + w1 * s1.z) + (w2 * s2.z + w3 * s3.z);
        acc.w += (w0 * s0.w + w1 * s1.w) + (w2 * s2.w + w3 * s3.w);
    }
    for (; m < mh; m++) {
        int t = __shfl_sync(hm, idx0, hb + m);
        float w = __ldg(&d_SC[(size_t)(start + 2 * m + half) * 4 + intent]) *
                  rsqrtf(__ldg(&d_deg2[t * 4 + intent]));
        float4 s = __ldg(&ego_row(Gu, Gi, t)[c]);
        acc.x += w * s.x; acc.y += w * s.y; acc.z += w * s.z; acc.w += w * s.w;
    }
    for (int j = start + 32 + half; j < end; j += 2) {     // overflow
        int t = __ldg(&d_sorted_t[j]);
        float w = __ldg(&d_SC[(size_t)j * 4 + intent]) *
                  rsqrtf(__ldg(&d_deg2[t * 4 + intent]));
        float4 s = __ldg(&ego_row(Gu, Gi, t)[c]);
        acc.x += w * s.x; acc.y += w * s.y; acc.z += w * s.z; acc.w += w * s.w;
    }
    acc.x += __shfl_xor_sync(0xffffffffu, acc.x, 16);
    acc.y += __shfl_xor_sync(0xffffffffu, acc.y, 16);
    acc.z += __shfl_xor_sync(0xffffffffu, acc.z, 16);
    acc.w += __shfl_xor_sync(0xffffffffu, acc.w, 16);
    if (half == 0) {
        float r2 = rsqrtf(d_deg2[wid * 4 + intent]);
        float4 a = __ldg(&ego_row(Gu, Gi, wid)[c]);
        reinterpret_cast<float4*>(out)[(size_t)wid * 16 + c] =
            make_float4(0.5f * (a.x + r2 * acc.x), 0.5f * (a.y + r2 * acc.y),
                        0.5f * (a.z + r2 * acc.z), 0.5f * (a.w + r2 * acc.w));
    }
}

extern "C" void kernel_launch(void* const* d_in, const int* in_sizes, int n_in,
                              void* d_out, int out_size) {
    const float* Gu = (const float*)d_in[0];
    const float* Gi = (const float*)d_in[1];
    const int*   eh = (const int*)d_in[2];
    const int*   et = (const int*)d_in[3];
    float* out = (float*)d_out;

    void* degp = nullptr;
    cudaGetSymbolAddress(&degp, d_deg);
    cudaMemsetAsync(degp, 0, NN * sizeof(int));

    const int T = 256;
    const int ROWG = (NN * 32 + T - 1) / T;   // warp-per-row grids
    k_deg         <<<(EE / 4 + T - 1) / T, T>>>(eh);
    k_s1          <<<NB, 256>>>();
    k_scan        <<<NB, 256>>>();
    k_scatter_node<<<SCAT_BLKS + NODE_BLKS, T>>>(eh, et, Gu, Gi);
    k_row1attn    <<<ROWG, T>>>();
    k_row2        <<<ROWG, T>>>(Gu, Gi, out);
}